// round 14
// baseline (speedup 1.0000x reference)
#include <cuda_runtime.h>
#include <cuda_bf16.h>

#define B_BAGS 16384
#define OUT_STRIDE 288
#define OFF_STRIDE 16400  // per-table offset stride, 16B-aligned

// Exclusive offsets per table: g_off[t*OFF_STRIDE + b], entries [0..B_BAGS]
__device__ __align__(16) int g_off[4 * OFF_STRIDE];

// ---------------------------------------------------------------------------
// Scan: one block per table, 1024 threads, 16 lens per thread, int4 I/O.
// ---------------------------------------------------------------------------
__global__ void scan_kernel(const int* __restrict__ l0, const int* __restrict__ l1,
                            const int* __restrict__ l2, const int* __restrict__ l3) {
    int t = blockIdx.x;
    const int* lens = (t == 0) ? l0 : (t == 1) ? l1 : (t == 2) ? l2 : l3;
    __shared__ int warp_sums[32];
    int i = threadIdx.x;
    int lane = i & 31;
    int wid = i >> 5;

    const int4* lens4 = reinterpret_cast<const int4*>(lens) + i * 4;
    int4 a0 = __ldg(lens4 + 0);
    int4 a1 = __ldg(lens4 + 1);
    int4 a2 = __ldg(lens4 + 2);
    int4 a3 = __ldg(lens4 + 3);

    int local[16] = {a0.x, a0.y, a0.z, a0.w, a1.x, a1.y, a1.z, a1.w,
                     a2.x, a2.y, a2.z, a2.w, a3.x, a3.y, a3.z, a3.w};
    int s = 0;
#pragma unroll
    for (int j = 0; j < 16; j++) s += local[j];

    int inc = s;
#pragma unroll
    for (int d = 1; d < 32; d <<= 1) {
        int v = __shfl_up_sync(0xffffffffu, inc, d);
        if (lane >= d) inc += v;
    }
    if (lane == 31) warp_sums[wid] = inc;
    __syncthreads();

    if (wid == 0) {
        int ws = warp_sums[lane];
        int winc = ws;
#pragma unroll
        for (int d = 1; d < 32; d <<= 1) {
            int v = __shfl_up_sync(0xffffffffu, winc, d);
            if (lane >= d) winc += v;
        }
        warp_sums[lane] = winc - ws;
    }
    __syncthreads();

    int run = warp_sums[wid] + (inc - s);
    int* off = g_off + t * OFF_STRIDE;

    int o[16];
#pragma unroll
    for (int j = 0; j < 16; j++) {
        o[j] = run;
        run += local[j];
    }
    int4* off4 = reinterpret_cast<int4*>(off + i * 16);
    off4[0] = make_int4(o[0], o[1], o[2], o[3]);
    off4[1] = make_int4(o[4], o[5], o[6], o[7]);
    off4[2] = make_int4(o[8], o[9], o[10], o[11]);
    off4[3] = make_int4(o[12], o[13], o[14], o[15]);
    if (i == 1023) off[B_BAGS] = run;
}

// ---------------------------------------------------------------------------
// Pooling helpers. MODE: 0 = default cached (__ldg), 2 = L2-bypass (__ldcv,
// no allocation at any level -> cannot displace the W1/W2 resident set).
// ---------------------------------------------------------------------------
template <int VEC, int MODE>
__device__ __forceinline__ void vload(float* d, const float* __restrict__ p) {
    if constexpr (VEC == 1) {
        d[0] = (MODE == 2) ? __ldcv(p) : __ldg(p);
    } else if constexpr (VEC == 2) {
        float2 v = (MODE == 2) ? __ldcv(reinterpret_cast<const float2*>(p))
                               : __ldg(reinterpret_cast<const float2*>(p));
        d[0] = v.x; d[1] = v.y;
    } else {
        float4 v = (MODE == 2) ? __ldcv(reinterpret_cast<const float4*>(p))
                               : __ldg(reinterpret_cast<const float4*>(p));
        d[0] = v.x; d[1] = v.y; d[2] = v.z; d[3] = v.w;
    }
}

template <int VEC>
__device__ __forceinline__ void vstore(float* __restrict__ p, const float* d) {
    if constexpr (VEC == 1) {
        __stcs(p, d[0]);
    } else if constexpr (VEC == 2) {
        float2 v; v.x = d[0]; v.y = d[1];
        __stcs(reinterpret_cast<float2*>(p), v);
    } else {
        float4 v; v.x = d[0]; v.y = d[1]; v.z = d[2]; v.w = d[3];
        __stcs(reinterpret_cast<float4*>(p), v);
    }
}

template <int VEC, int MODE>
__device__ __forceinline__ void pool_bag(const float* __restrict__ W,
                                         const int* __restrict__ ids, int len,
                                         float* __restrict__ o, int lane) {
    constexpr int DIM = 32 * VEC;
    const int col = lane * VEC;
    float acc[VEC];
#pragma unroll
    for (int v = 0; v < VEC; v++) acc[v] = 0.f;

    int k = 0;
    for (; k + 4 <= len; k += 4) {
        int id0 = __ldcs(ids + k + 0);
        int id1 = __ldcs(ids + k + 1);
        int id2 = __ldcs(ids + k + 2);
        int id3 = __ldcs(ids + k + 3);
        float t0[VEC], t1[VEC], t2[VEC], t3[VEC];
        vload<VEC, MODE>(t0, W + (size_t)id0 * DIM + col);
        vload<VEC, MODE>(t1, W + (size_t)id1 * DIM + col);
        vload<VEC, MODE>(t2, W + (size_t)id2 * DIM + col);
        vload<VEC, MODE>(t3, W + (size_t)id3 * DIM + col);
#pragma unroll
        for (int v = 0; v < VEC; v++) acc[v] += (t0[v] + t1[v]) + (t2[v] + t3[v]);
    }
    for (; k < len; k++) {
        float tv[VEC];
        vload<VEC, MODE>(tv, W + (size_t)__ldcs(ids + k) * DIM + col);
#pragma unroll
        for (int v = 0; v < VEC; v++) acc[v] += tv[v];
    }
    vstore<VEC>(o + col, acc);
}

// ---------------------------------------------------------------------------
// Schedule: Phase A (warps 0..40959) = all T1/T2 bags (cached) interleaved 4:1
// with 25% of T0/T3 loaded via L2-BYPASS (.cv) — soaks phase A's ~88MB of
// spare DRAM capacity without allocating in L2, so W1/W2 residency is intact.
// Phase B (warps 40960..65535) = remaining 75% of T0/T3, default-cached to
// keep the measured ~1.46x row-reuse capture.
// ---------------------------------------------------------------------------
__global__ void __launch_bounds__(256)
pool_kernel(const float* __restrict__ W0, const float* __restrict__ W1,
            const float* __restrict__ W2, const float* __restrict__ W3,
            const int* __restrict__ I0, const int* __restrict__ I1,
            const int* __restrict__ I2, const int* __restrict__ I3,
            float* __restrict__ out) {
    int g = blockIdx.x * (blockDim.x >> 5) + (threadIdx.x >> 5);
    int lane = threadIdx.x & 31;

    int t, bag;
    bool bypass = false;
    if (g < 40960) {
        int q = g / 5;
        int r = g - q * 5;
        if (r < 4) {                 // cached leg: T1/T2, all 32768 bags
            int idx = q * 4 + r;
            t = (idx & 1) ? 2 : 1;
            bag = idx >> 1;
        } else {                     // bypass stream leg: first 4096 bags of T0/T3
            t = (q & 1) ? 3 : 0;
            bag = q >> 1;
            bypass = true;
        }
    } else {                         // phase B: bags 4096..16383 of T0/T3, cached
        int h = g - 40960;
        t = (h & 1) ? 3 : 0;
        bag = 4096 + (h >> 1);
    }

    const int* off = g_off + t * OFF_STRIDE;
    int o0 = off[bag];
    int len = off[bag + 1] - o0;
    float* obase = out + (size_t)bag * OUT_STRIDE;

    if (bypass) {
        if (t == 0) pool_bag<2, 2>(W0, I0 + o0, len, obase + 0, lane);
        else        pool_bag<2, 2>(W3, I3 + o0, len, obase + 224, lane);
    } else {
        switch (t) {
            case 0: pool_bag<2, 0>(W0, I0 + o0, len, obase + 0, lane); break;   // dim 64
            case 1: pool_bag<4, 0>(W1, I1 + o0, len, obase + 64, lane); break;  // dim 128
            case 2: pool_bag<1, 0>(W2, I2 + o0, len, obase + 192, lane); break; // dim 32
            case 3: pool_bag<2, 0>(W3, I3 + o0, len, obase + 224, lane); break; // dim 64
        }
    }
}

// ---------------------------------------------------------------------------
extern "C" void kernel_launch(void* const* d_in, const int* in_sizes, int n_in,
                              void* d_out, int out_size) {
    const float *W0, *W1, *W2, *W3;
    const int *I0, *I1, *I2, *I3, *L0, *L1, *L2, *L3;

    if (in_sizes[2] == B_BAGS) {
        // interleaved (W0,ids0,lens0,W1,...)
        W0 = (const float*)d_in[0]; I0 = (const int*)d_in[1];  L0 = (const int*)d_in[2];
        W1 = (const float*)d_in[3]; I1 = (const int*)d_in[4];  L1 = (const int*)d_in[5];
        W2 = (const float*)d_in[6]; I2 = (const int*)d_in[7];  L2 = (const int*)d_in[8];
        W3 = (const float*)d_in[9]; I3 = (const int*)d_in[10]; L3 = (const int*)d_in[11];
    } else {
        // grouped (reference signature order)
        W0 = (const float*)d_in[0]; W1 = (const float*)d_in[1];
        W2 = (const float*)d_in[2]; W3 = (const float*)d_in[3];
        I0 = (const int*)d_in[4];   I1 = (const int*)d_in[5];
        I2 = (const int*)d_in[6];   I3 = (const int*)d_in[7];
        L0 = (const int*)d_in[8];   L1 = (const int*)d_in[9];
        L2 = (const int*)d_in[10];  L3 = (const int*)d_in[11];
    }

    float* out = (float*)d_out;

    scan_kernel<<<4, 1024>>>(L0, L1, L2, L3);
    pool_kernel<<<8192, 256>>>(W0, W1, W2, W3, I0, I1, I2, I3, out);
}

// round 15
// speedup vs baseline: 1.1122x; 1.1122x over previous
#include <cuda_runtime.h>
#include <cuda_bf16.h>

#define B_BAGS 16384
#define OUT_STRIDE 288
#define OFF_STRIDE 16400  // per-table offset stride, 16B-aligned (16400*4 % 16 == 0)

// Exclusive offsets per table: g_off[t*OFF_STRIDE + b], entries [0..B_BAGS]
__device__ __align__(16) int g_off[4 * OFF_STRIDE];

// ---------------------------------------------------------------------------
// Scan: one block per table, 1024 threads, 16 lens per thread.
// Fully vectorized int4 loads/stores, two-level warp-shuffle scan.
// ---------------------------------------------------------------------------
__global__ void scan_kernel(const int* __restrict__ l0, const int* __restrict__ l1,
                            const int* __restrict__ l2, const int* __restrict__ l3) {
    int t = blockIdx.x;
    const int* lens = (t == 0) ? l0 : (t == 1) ? l1 : (t == 2) ? l2 : l3;
    __shared__ int warp_sums[32];
    int i = threadIdx.x;
    int lane = i & 31;
    int wid = i >> 5;

    const int4* lens4 = reinterpret_cast<const int4*>(lens) + i * 4;
    int4 a0 = __ldg(lens4 + 0);
    int4 a1 = __ldg(lens4 + 1);
    int4 a2 = __ldg(lens4 + 2);
    int4 a3 = __ldg(lens4 + 3);

    int local[16] = {a0.x, a0.y, a0.z, a0.w, a1.x, a1.y, a1.z, a1.w,
                     a2.x, a2.y, a2.z, a2.w, a3.x, a3.y, a3.z, a3.w};
    int s = 0;
#pragma unroll
    for (int j = 0; j < 16; j++) s += local[j];

    int inc = s;
#pragma unroll
    for (int d = 1; d < 32; d <<= 1) {
        int v = __shfl_up_sync(0xffffffffu, inc, d);
        if (lane >= d) inc += v;
    }
    if (lane == 31) warp_sums[wid] = inc;
    __syncthreads();

    if (wid == 0) {
        int ws = warp_sums[lane];
        int winc = ws;
#pragma unroll
        for (int d = 1; d < 32; d <<= 1) {
            int v = __shfl_up_sync(0xffffffffu, winc, d);
            if (lane >= d) winc += v;
        }
        warp_sums[lane] = winc - ws;
    }
    __syncthreads();

    int run = warp_sums[wid] + (inc - s);
    int* off = g_off + t * OFF_STRIDE;

    int o[16];
#pragma unroll
    for (int j = 0; j < 16; j++) {
        o[j] = run;
        run += local[j];
    }
    int4* off4 = reinterpret_cast<int4*>(off + i * 16);
    off4[0] = make_int4(o[0], o[1], o[2], o[3]);
    off4[1] = make_int4(o[4], o[5], o[6], o[7]);
    off4[2] = make_int4(o[8], o[9], o[10], o[11]);
    off4[3] = make_int4(o[12], o[13], o[14], o[15]);
    if (i == 1023) off[B_BAGS] = run;
}

// ---------------------------------------------------------------------------
// Pooling helpers (R9 proven-best configuration).
// ---------------------------------------------------------------------------
template <int VEC>
__device__ __forceinline__ void vload(float* d, const float* __restrict__ p) {
    if constexpr (VEC == 1) {
        d[0] = __ldg(p);
    } else if constexpr (VEC == 2) {
        float2 v = __ldg(reinterpret_cast<const float2*>(p));
        d[0] = v.x; d[1] = v.y;
    } else {
        float4 v = __ldg(reinterpret_cast<const float4*>(p));
        d[0] = v.x; d[1] = v.y; d[2] = v.z; d[3] = v.w;
    }
}

template <int VEC>
__device__ __forceinline__ void vstore(float* __restrict__ p, const float* d) {
    if constexpr (VEC == 1) {
        __stcs(p, d[0]);
    } else if constexpr (VEC == 2) {
        float2 v; v.x = d[0]; v.y = d[1];
        __stcs(reinterpret_cast<float2*>(p), v);
    } else {
        float4 v; v.x = d[0]; v.y = d[1]; v.z = d[2]; v.w = d[3];
        __stcs(reinterpret_cast<float4*>(p), v);
    }
}

template <int VEC>
__device__ __forceinline__ void pool_bag(const float* __restrict__ W,
                                         const int* __restrict__ ids, int len,
                                         float* __restrict__ o, int lane) {
    constexpr int DIM = 32 * VEC;
    const int col = lane * VEC;
    float acc[VEC];
#pragma unroll
    for (int v = 0; v < VEC; v++) acc[v] = 0.f;

    int k = 0;
    for (; k + 4 <= len; k += 4) {
        int id0 = __ldcs(ids + k + 0);
        int id1 = __ldcs(ids + k + 1);
        int id2 = __ldcs(ids + k + 2);
        int id3 = __ldcs(ids + k + 3);
        float t0[VEC], t1[VEC], t2[VEC], t3[VEC];
        vload<VEC>(t0, W + (size_t)id0 * DIM + col);
        vload<VEC>(t1, W + (size_t)id1 * DIM + col);
        vload<VEC>(t2, W + (size_t)id2 * DIM + col);
        vload<VEC>(t3, W + (size_t)id3 * DIM + col);
#pragma unroll
        for (int v = 0; v < VEC; v++) acc[v] += (t0[v] + t1[v]) + (t2[v] + t3[v]);
    }
    for (; k < len; k++) {
        float tv[VEC];
        vload<VEC>(tv, W + (size_t)__ldcs(ids + k) * DIM + col);
#pragma unroll
        for (int v = 0; v < VEC; v++) acc[v] += tv[v];
    }
    vstore<VEC>(o + col, acc);
}

// ---------------------------------------------------------------------------
// Windowed schedule (measured optimum): waves process one table at a time.
// T1 (51MB) and T2 (64MB) first -> L2-resident during their windows; T0/T3
// after, default-cached to capture their ~1.46x intra-phase row reuse. All
// overlap variants (ldcs interleave, metered ldcs, metered ldcv) measurably
// inflated DRAM traffic past this config -- the 115/126MB resident set
// tolerates no concurrent streaming.
// ---------------------------------------------------------------------------
__global__ void __launch_bounds__(256)
pool_kernel(const float* __restrict__ W0, const float* __restrict__ W1,
            const float* __restrict__ W2, const float* __restrict__ W3,
            const int* __restrict__ I0, const int* __restrict__ I1,
            const int* __restrict__ I2, const int* __restrict__ I3,
            float* __restrict__ out) {
    int g = blockIdx.x * (blockDim.x >> 5) + (threadIdx.x >> 5);
    int lane = threadIdx.x & 31;

    int group = g >> 14;          // 16384 warps per table group
    int bag = g & (B_BAGS - 1);
    if (group >= 4) return;
    // group order: T1, T2, T0, T3
    int t = (group == 0) ? 1 : (group == 1) ? 2 : (group == 2) ? 0 : 3;

    const int* off = g_off + t * OFF_STRIDE;
    int o0 = off[bag];
    int len = off[bag + 1] - o0;
    float* obase = out + (size_t)bag * OUT_STRIDE;

    switch (t) {
        case 0: pool_bag<2>(W0, I0 + o0, len, obase + 0, lane); break;   // dim 64
        case 1: pool_bag<4>(W1, I1 + o0, len, obase + 64, lane); break;  // dim 128
        case 2: pool_bag<1>(W2, I2 + o0, len, obase + 192, lane); break; // dim 32
        case 3: pool_bag<2>(W3, I3 + o0, len, obase + 224, lane); break; // dim 64
    }
}

// ---------------------------------------------------------------------------
extern "C" void kernel_launch(void* const* d_in, const int* in_sizes, int n_in,
                              void* d_out, int out_size) {
    const float *W0, *W1, *W2, *W3;
    const int *I0, *I1, *I2, *I3, *L0, *L1, *L2, *L3;

    if (in_sizes[2] == B_BAGS) {
        // interleaved (W0,ids0,lens0,W1,...)
        W0 = (const float*)d_in[0]; I0 = (const int*)d_in[1];  L0 = (const int*)d_in[2];
        W1 = (const float*)d_in[3]; I1 = (const int*)d_in[4];  L1 = (const int*)d_in[5];
        W2 = (const float*)d_in[6]; I2 = (const int*)d_in[7];  L2 = (const int*)d_in[8];
        W3 = (const float*)d_in[9]; I3 = (const int*)d_in[10]; L3 = (const int*)d_in[11];
    } else {
        // grouped (reference signature order)
        W0 = (const float*)d_in[0]; W1 = (const float*)d_in[1];
        W2 = (const float*)d_in[2]; W3 = (const float*)d_in[3];
        I0 = (const int*)d_in[4];   I1 = (const int*)d_in[5];
        I2 = (const int*)d_in[6];   I3 = (const int*)d_in[7];
        L0 = (const int*)d_in[8];   L1 = (const int*)d_in[9];
        L2 = (const int*)d_in[10];  L3 = (const int*)d_in[11];
    }

    float* out = (float*)d_out;

    scan_kernel<<<4, 1024>>>(L0, L1, L2, L3);
    pool_kernel<<<8192, 256>>>(W0, W1, W2, W3, I0, I1, I2, I3, out);
}

// round 16
// speedup vs baseline: 1.1720x; 1.0538x over previous
#include <cuda_runtime.h>
#include <cuda_bf16.h>

#define B_BAGS 16384
#define OUT_STRIDE 288
#define OFF_STRIDE 16400  // per-table offset stride, 16B-aligned

// Exclusive offsets per table: g_off[t*OFF_STRIDE + b], entries [0..B_BAGS]
__device__ __align__(16) int g_off[4 * OFF_STRIDE];

// ---------------------------------------------------------------------------
// Scan: one block per table, 1024 threads, 16 lens per thread, int4 I/O.
// ---------------------------------------------------------------------------
__global__ void scan_kernel(const int* __restrict__ l0, const int* __restrict__ l1,
                            const int* __restrict__ l2, const int* __restrict__ l3) {
    int t = blockIdx.x;
    const int* lens = (t == 0) ? l0 : (t == 1) ? l1 : (t == 2) ? l2 : l3;
    __shared__ int warp_sums[32];
    int i = threadIdx.x;
    int lane = i & 31;
    int wid = i >> 5;

    const int4* lens4 = reinterpret_cast<const int4*>(lens) + i * 4;
    int4 a0 = __ldg(lens4 + 0);
    int4 a1 = __ldg(lens4 + 1);
    int4 a2 = __ldg(lens4 + 2);
    int4 a3 = __ldg(lens4 + 3);

    int local[16] = {a0.x, a0.y, a0.z, a0.w, a1.x, a1.y, a1.z, a1.w,
                     a2.x, a2.y, a2.z, a2.w, a3.x, a3.y, a3.z, a3.w};
    int s = 0;
#pragma unroll
    for (int j = 0; j < 16; j++) s += local[j];

    int inc = s;
#pragma unroll
    for (int d = 1; d < 32; d <<= 1) {
        int v = __shfl_up_sync(0xffffffffu, inc, d);
        if (lane >= d) inc += v;
    }
    if (lane == 31) warp_sums[wid] = inc;
    __syncthreads();

    if (wid == 0) {
        int ws = warp_sums[lane];
        int winc = ws;
#pragma unroll
        for (int d = 1; d < 32; d <<= 1) {
            int v = __shfl_up_sync(0xffffffffu, winc, d);
            if (lane >= d) winc += v;
        }
        warp_sums[lane] = winc - ws;
    }
    __syncthreads();

    int run = warp_sums[wid] + (inc - s);
    int* off = g_off + t * OFF_STRIDE;

    int o[16];
#pragma unroll
    for (int j = 0; j < 16; j++) {
        o[j] = run;
        run += local[j];
    }
    int4* off4 = reinterpret_cast<int4*>(off + i * 16);
    off4[0] = make_int4(o[0], o[1], o[2], o[3]);
    off4[1] = make_int4(o[4], o[5], o[6], o[7]);
    off4[2] = make_int4(o[8], o[9], o[10], o[11]);
    off4[3] = make_int4(o[12], o[13], o[14], o[15]);
    if (i == 1023) off[B_BAGS] = run;
}

// ---------------------------------------------------------------------------
// Pooling helpers (R9 proven-best configuration for T0/T1/T3).
// ---------------------------------------------------------------------------
template <int VEC>
__device__ __forceinline__ void vload(float* d, const float* __restrict__ p) {
    if constexpr (VEC == 1) {
        d[0] = __ldg(p);
    } else if constexpr (VEC == 2) {
        float2 v = __ldg(reinterpret_cast<const float2*>(p));
        d[0] = v.x; d[1] = v.y;
    } else {
        float4 v = __ldg(reinterpret_cast<const float4*>(p));
        d[0] = v.x; d[1] = v.y; d[2] = v.z; d[3] = v.w;
    }
}

template <int VEC>
__device__ __forceinline__ void vstore(float* __restrict__ p, const float* d) {
    if constexpr (VEC == 1) {
        __stcs(p, d[0]);
    } else if constexpr (VEC == 2) {
        float2 v; v.x = d[0]; v.y = d[1];
        __stcs(reinterpret_cast<float2*>(p), v);
    } else {
        float4 v; v.x = d[0]; v.y = d[1]; v.z = d[2]; v.w = d[3];
        __stcs(reinterpret_cast<float4*>(p), v);
    }
}

template <int VEC>
__device__ __forceinline__ void pool_bag(const float* __restrict__ W,
                                         const int* __restrict__ ids, int len,
                                         float* __restrict__ o, int lane) {
    constexpr int DIM = 32 * VEC;
    const int col = lane * VEC;
    float acc[VEC];
#pragma unroll
    for (int v = 0; v < VEC; v++) acc[v] = 0.f;

    int k = 0;
    for (; k + 4 <= len; k += 4) {
        int id0 = __ldcs(ids + k + 0);
        int id1 = __ldcs(ids + k + 1);
        int id2 = __ldcs(ids + k + 2);
        int id3 = __ldcs(ids + k + 3);
        float t0[VEC], t1[VEC], t2[VEC], t3[VEC];
        vload<VEC>(t0, W + (size_t)id0 * DIM + col);
        vload<VEC>(t1, W + (size_t)id1 * DIM + col);
        vload<VEC>(t2, W + (size_t)id2 * DIM + col);
        vload<VEC>(t3, W + (size_t)id3 * DIM + col);
#pragma unroll
        for (int v = 0; v < VEC; v++) acc[v] += (t0[v] + t1[v]) + (t2[v] + t3[v]);
    }
    for (; k < len; k++) {
        float tv[VEC];
        vload<VEC>(tv, W + (size_t)__ldcs(ids + k) * DIM + col);
#pragma unroll
        for (int v = 0; v < VEC; v++) acc[v] += tv[v];
    }
    vstore<VEC>(o + col, acc);
}

// T2 (dim 32) row-paired pooling: lanes 0-15 handle even rows, 16-31 odd rows,
// each lane loading float2 -> one warp-load fetches TWO 128B rows (256B),
// halving issue count and doubling per-warp bytes-in-flight in the L2-latency-
// bound T2 window. Halves merged once at the end via shfl_xor(16).
__device__ __forceinline__ void pool_bag_t2(const float* __restrict__ W,
                                            const int* __restrict__ ids, int len,
                                            float* __restrict__ o, int lane) {
    int half = lane >> 4;       // 0 = even-index rows, 1 = odd-index rows
    int sub = lane & 15;        // column-pair index
    const int col = sub * 2;
    float ax = 0.f, ay = 0.f;

    int k = 0;
    for (; k + 8 <= len; k += 8) {   // 8 rows per iteration, 4 warp-loads
        int i0 = __ldcs(ids + k + 0 + half);
        int i1 = __ldcs(ids + k + 2 + half);
        int i2 = __ldcs(ids + k + 4 + half);
        int i3 = __ldcs(ids + k + 6 + half);
        float2 v0 = __ldg(reinterpret_cast<const float2*>(W + (size_t)i0 * 32 + col));
        float2 v1 = __ldg(reinterpret_cast<const float2*>(W + (size_t)i1 * 32 + col));
        float2 v2 = __ldg(reinterpret_cast<const float2*>(W + (size_t)i2 * 32 + col));
        float2 v3 = __ldg(reinterpret_cast<const float2*>(W + (size_t)i3 * 32 + col));
        ax += (v0.x + v1.x) + (v2.x + v3.x);
        ay += (v0.y + v1.y) + (v2.y + v3.y);
    }
    for (; k + 2 <= len; k += 2) {   // 2 rows per step
        int i = __ldcs(ids + k + half);
        float2 v = __ldg(reinterpret_cast<const float2*>(W + (size_t)i * 32 + col));
        ax += v.x; ay += v.y;
    }
    if (k < len && half == 0) {      // odd leftover row: even half only
        int i = __ldcs(ids + k);
        float2 v = __ldg(reinterpret_cast<const float2*>(W + (size_t)i * 32 + col));
        ax += v.x; ay += v.y;
    }

    ax += __shfl_xor_sync(0xffffffffu, ax, 16);
    ay += __shfl_xor_sync(0xffffffffu, ay, 16);
    if (half == 0) {
        float2 r; r.x = ax; r.y = ay;
        __stcs(reinterpret_cast<float2*>(o + col), r);
    }
}

// ---------------------------------------------------------------------------
// Windowed schedule (measured optimum): T1, T2 windows first (L2-resident),
// then T0, T3 windows default-cached (capture ~1.46x row reuse).
// ---------------------------------------------------------------------------
__global__ void __launch_bounds__(256)
pool_kernel(const float* __restrict__ W0, const float* __restrict__ W1,
            const float* __restrict__ W2, const float* __restrict__ W3,
            const int* __restrict__ I0, const int* __restrict__ I1,
            const int* __restrict__ I2, const int* __restrict__ I3,
            float* __restrict__ out) {
    int g = blockIdx.x * (blockDim.x >> 5) + (threadIdx.x >> 5);
    int lane = threadIdx.x & 31;

    int group = g >> 14;          // 16384 warps per table group
    int bag = g & (B_BAGS - 1);
    if (group >= 4) return;
    // group order: T1, T2, T0, T3
    int t = (group == 0) ? 1 : (group == 1) ? 2 : (group == 2) ? 0 : 3;

    const int* off = g_off + t * OFF_STRIDE;
    int o0 = off[bag];
    int len = off[bag + 1] - o0;
    float* obase = out + (size_t)bag * OUT_STRIDE;

    switch (t) {
        case 0: pool_bag<2>(W0, I0 + o0, len, obase + 0, lane); break;    // dim 64
        case 1: pool_bag<4>(W1, I1 + o0, len, obase + 64, lane); break;   // dim 128
        case 2: pool_bag_t2(W2, I2 + o0, len, obase + 192, lane); break;  // dim 32, paired
        case 3: pool_bag<2>(W3, I3 + o0, len, obase + 224, lane); break;  // dim 64
    }
}

// ---------------------------------------------------------------------------
extern "C" void kernel_launch(void* const* d_in, const int* in_sizes, int n_in,
                              void* d_out, int out_size) {
    const float *W0, *W1, *W2, *W3;
    const int *I0, *I1, *I2, *I3, *L0, *L1, *L2, *L3;

    if (in_sizes[2] == B_BAGS) {
        // interleaved (W0,ids0,lens0,W1,...)
        W0 = (const float*)d_in[0]; I0 = (const int*)d_in[1];  L0 = (const int*)d_in[2];
        W1 = (const float*)d_in[3]; I1 = (const int*)d_in[4];  L1 = (const int*)d_in[5];
        W2 = (const float*)d_in[6]; I2 = (const int*)d_in[7];  L2 = (const int*)d_in[8];
        W3 = (const float*)d_in[9]; I3 = (const int*)d_in[10]; L3 = (const int*)d_in[11];
    } else {
        // grouped (reference signature order)
        W0 = (const float*)d_in[0]; W1 = (const float*)d_in[1];
        W2 = (const float*)d_in[2]; W3 = (const float*)d_in[3];
        I0 = (const int*)d_in[4];   I1 = (const int*)d_in[5];
        I2 = (const int*)d_in[6];   I3 = (const int*)d_in[7];
        L0 = (const int*)d_in[8];   L1 = (const int*)d_in[9];
        L2 = (const int*)d_in[10];  L3 = (const int*)d_in[11];
    }

    float* out = (float*)d_out;

    scan_kernel<<<4, 1024>>>(L0, L1, L2, L3);
    pool_kernel<<<8192, 256>>>(W0, W1, W2, W3, I0, I1, I2, I3, out);
}

// round 17
// speedup vs baseline: 1.1923x; 1.0173x over previous
#include <cuda_runtime.h>
#include <cuda_bf16.h>

#define B_BAGS 16384
#define OUT_STRIDE 288
#define OFF_STRIDE 16400  // per-table offset stride, 16B-aligned

// Exclusive offsets per table: g_off[t*OFF_STRIDE + b], entries [0..B_BAGS]
__device__ __align__(16) int g_off[4 * OFF_STRIDE];

// ---------------------------------------------------------------------------
// Scan: one block per table, 1024 threads, 16 lens per thread, int4 I/O.
// ---------------------------------------------------------------------------
__global__ void scan_kernel(const int* __restrict__ l0, const int* __restrict__ l1,
                            const int* __restrict__ l2, const int* __restrict__ l3) {
    int t = blockIdx.x;
    const int* lens = (t == 0) ? l0 : (t == 1) ? l1 : (t == 2) ? l2 : l3;
    __shared__ int warp_sums[32];
    int i = threadIdx.x;
    int lane = i & 31;
    int wid = i >> 5;

    const int4* lens4 = reinterpret_cast<const int4*>(lens) + i * 4;
    int4 a0 = __ldg(lens4 + 0);
    int4 a1 = __ldg(lens4 + 1);
    int4 a2 = __ldg(lens4 + 2);
    int4 a3 = __ldg(lens4 + 3);

    int local[16] = {a0.x, a0.y, a0.z, a0.w, a1.x, a1.y, a1.z, a1.w,
                     a2.x, a2.y, a2.z, a2.w, a3.x, a3.y, a3.z, a3.w};
    int s = 0;
#pragma unroll
    for (int j = 0; j < 16; j++) s += local[j];

    int inc = s;
#pragma unroll
    for (int d = 1; d < 32; d <<= 1) {
        int v = __shfl_up_sync(0xffffffffu, inc, d);
        if (lane >= d) inc += v;
    }
    if (lane == 31) warp_sums[wid] = inc;
    __syncthreads();

    if (wid == 0) {
        int ws = warp_sums[lane];
        int winc = ws;
#pragma unroll
        for (int d = 1; d < 32; d <<= 1) {
            int v = __shfl_up_sync(0xffffffffu, winc, d);
            if (lane >= d) winc += v;
        }
        warp_sums[lane] = winc - ws;
    }
    __syncthreads();

    int run = warp_sums[wid] + (inc - s);
    int* off = g_off + t * OFF_STRIDE;

    int o[16];
#pragma unroll
    for (int j = 0; j < 16; j++) {
        o[j] = run;
        run += local[j];
    }
    int4* off4 = reinterpret_cast<int4*>(off + i * 16);
    off4[0] = make_int4(o[0], o[1], o[2], o[3]);
    off4[1] = make_int4(o[4], o[5], o[6], o[7]);
    off4[2] = make_int4(o[8], o[9], o[10], o[11]);
    off4[3] = make_int4(o[12], o[13], o[14], o[15]);
    if (i == 1023) off[B_BAGS] = run;
}

// ---------------------------------------------------------------------------
// T1 (dim 128): one warp per bag, float4 per lane (512B per warp-load).
// ---------------------------------------------------------------------------
__device__ __forceinline__ void pool_bag_t1(const float* __restrict__ W,
                                            const int* __restrict__ ids, int len,
                                            float* __restrict__ o, int lane) {
    const int col = lane * 4;
    float4 acc = make_float4(0.f, 0.f, 0.f, 0.f);

    int k = 0;
    for (; k + 4 <= len; k += 4) {
        int id0 = __ldcs(ids + k + 0);
        int id1 = __ldcs(ids + k + 1);
        int id2 = __ldcs(ids + k + 2);
        int id3 = __ldcs(ids + k + 3);
        float4 v0 = __ldg(reinterpret_cast<const float4*>(W + (size_t)id0 * 128 + col));
        float4 v1 = __ldg(reinterpret_cast<const float4*>(W + (size_t)id1 * 128 + col));
        float4 v2 = __ldg(reinterpret_cast<const float4*>(W + (size_t)id2 * 128 + col));
        float4 v3 = __ldg(reinterpret_cast<const float4*>(W + (size_t)id3 * 128 + col));
        acc.x += (v0.x + v1.x) + (v2.x + v3.x);
        acc.y += (v0.y + v1.y) + (v2.y + v3.y);
        acc.z += (v0.z + v1.z) + (v2.z + v3.z);
        acc.w += (v0.w + v1.w) + (v2.w + v3.w);
    }
    for (; k < len; k++) {
        int id = __ldcs(ids + k);
        float4 v = __ldg(reinterpret_cast<const float4*>(W + (size_t)id * 128 + col));
        acc.x += v.x; acc.y += v.y; acc.z += v.z; acc.w += v.w;
    }
    __stcs(reinterpret_cast<float4*>(o + col), acc);
}

// ---------------------------------------------------------------------------
// T0/T3 (dim 64) row-paired: lanes 0-15 even rows, 16-31 odd rows, float4 per
// lane -> one warp-load fetches TWO 256B rows (512B). Halves issue count and
// doubles per-warp bytes-in-flight. Merge via shfl_xor(16) at the end.
// ---------------------------------------------------------------------------
__device__ __forceinline__ void pool_bag_d64(const float* __restrict__ W,
                                             const int* __restrict__ ids, int len,
                                             float* __restrict__ o, int lane) {
    int half = lane >> 4;       // 0 = even-index rows, 1 = odd-index rows
    int sub = lane & 15;
    const int col = sub * 4;    // 16 lanes x 4 floats = 64 cols
    float4 acc = make_float4(0.f, 0.f, 0.f, 0.f);

    int k = 0;
    for (; k + 8 <= len; k += 8) {   // 8 rows per iteration, 4 warp-loads
        int i0 = __ldcs(ids + k + 0 + half);
        int i1 = __ldcs(ids + k + 2 + half);
        int i2 = __ldcs(ids + k + 4 + half);
        int i3 = __ldcs(ids + k + 6 + half);
        float4 v0 = __ldg(reinterpret_cast<const float4*>(W + (size_t)i0 * 64 + col));
        float4 v1 = __ldg(reinterpret_cast<const float4*>(W + (size_t)i1 * 64 + col));
        float4 v2 = __ldg(reinterpret_cast<const float4*>(W + (size_t)i2 * 64 + col));
        float4 v3 = __ldg(reinterpret_cast<const float4*>(W + (size_t)i3 * 64 + col));
        acc.x += (v0.x + v1.x) + (v2.x + v3.x);
        acc.y += (v0.y + v1.y) + (v2.y + v3.y);
        acc.z += (v0.z + v1.z) + (v2.z + v3.z);
        acc.w += (v0.w + v1.w) + (v2.w + v3.w);
    }
    for (; k + 2 <= len; k += 2) {
        int i = __ldcs(ids + k + half);
        float4 v = __ldg(reinterpret_cast<const float4*>(W + (size_t)i * 64 + col));
        acc.x += v.x; acc.y += v.y; acc.z += v.z; acc.w += v.w;
    }
    if (k < len && half == 0) {      // odd leftover row: even half only
        int i = __ldcs(ids + k);
        float4 v = __ldg(reinterpret_cast<const float4*>(W + (size_t)i * 64 + col));
        acc.x += v.x; acc.y += v.y; acc.z += v.z; acc.w += v.w;
    }

    acc.x += __shfl_xor_sync(0xffffffffu, acc.x, 16);
    acc.y += __shfl_xor_sync(0xffffffffu, acc.y, 16);
    acc.z += __shfl_xor_sync(0xffffffffu, acc.z, 16);
    acc.w += __shfl_xor_sync(0xffffffffu, acc.w, 16);
    if (half == 0) {
        __stcs(reinterpret_cast<float4*>(o + col), acc);
    }
}

// ---------------------------------------------------------------------------
// T2 (dim 32) row-paired: lanes 0-15 even rows, 16-31 odd rows, float2 per
// lane -> one warp-load fetches TWO 128B rows (256B). Proven +6us in R16.
// ---------------------------------------------------------------------------
__device__ __forceinline__ void pool_bag_t2(const float* __restrict__ W,
                                            const int* __restrict__ ids, int len,
                                            float* __restrict__ o, int lane) {
    int half = lane >> 4;
    int sub = lane & 15;
    const int col = sub * 2;
    float ax = 0.f, ay = 0.f;

    int k = 0;
    for (; k + 8 <= len; k += 8) {
        int i0 = __ldcs(ids + k + 0 + half);
        int i1 = __ldcs(ids + k + 2 + half);
        int i2 = __ldcs(ids + k + 4 + half);
        int i3 = __ldcs(ids + k + 6 + half);
        float2 v0 = __ldg(reinterpret_cast<const float2*>(W + (size_t)i0 * 32 + col));
        float2 v1 = __ldg(reinterpret_cast<const float2*>(W + (size_t)i1 * 32 + col));
        float2 v2 = __ldg(reinterpret_cast<const float2*>(W + (size_t)i2 * 32 + col));
        float2 v3 = __ldg(reinterpret_cast<const float2*>(W + (size_t)i3 * 32 + col));
        ax += (v0.x + v1.x) + (v2.x + v3.x);
        ay += (v0.y + v1.y) + (v2.y + v3.y);
    }
    for (; k + 2 <= len; k += 2) {
        int i = __ldcs(ids + k + half);
        float2 v = __ldg(reinterpret_cast<const float2*>(W + (size_t)i * 32 + col));
        ax += v.x; ay += v.y;
    }
    if (k < len && half == 0) {
        int i = __ldcs(ids + k);
        float2 v = __ldg(reinterpret_cast<const float2*>(W + (size_t)i * 32 + col));
        ax += v.x; ay += v.y;
    }

    ax += __shfl_xor_sync(0xffffffffu, ax, 16);
    ay += __shfl_xor_sync(0xffffffffu, ay, 16);
    if (half == 0) {
        float2 r; r.x = ax; r.y = ay;
        __stcs(reinterpret_cast<float2*>(o + col), r);
    }
}

// ---------------------------------------------------------------------------
// Windowed schedule (measured optimum): T1, T2 windows first (L2-resident),
// then T0, T3 windows default-cached (capture ~1.46x row reuse).
// ---------------------------------------------------------------------------
__global__ void __launch_bounds__(256)
pool_kernel(const float* __restrict__ W0, const float* __restrict__ W1,
            const float* __restrict__ W2, const float* __restrict__ W3,
            const int* __restrict__ I0, const int* __restrict__ I1,
            const int* __restrict__ I2, const int* __restrict__ I3,
            float* __restrict__ out) {
    int g = blockIdx.x * (blockDim.x >> 5) + (threadIdx.x >> 5);
    int lane = threadIdx.x & 31;

    int group = g >> 14;          // 16384 warps per table group
    int bag = g & (B_BAGS - 1);
    if (group >= 4) return;
    // group order: T1, T2, T0, T3
    int t = (group == 0) ? 1 : (group == 1) ? 2 : (group == 2) ? 0 : 3;

    const int* off = g_off + t * OFF_STRIDE;
    int o0 = off[bag];
    int len = off[bag + 1] - o0;
    float* obase = out + (size_t)bag * OUT_STRIDE;

    switch (t) {
        case 0: pool_bag_d64(W0, I0 + o0, len, obase + 0, lane); break;   // dim 64, paired
        case 1: pool_bag_t1 (W1, I1 + o0, len, obase + 64, lane); break;  // dim 128
        case 2: pool_bag_t2 (W2, I2 + o0, len, obase + 192, lane); break; // dim 32, paired
        case 3: pool_bag_d64(W3, I3 + o0, len, obase + 224, lane); break; // dim 64, paired
    }
}

// ---------------------------------------------------------------------------
extern "C" void kernel_launch(void* const* d_in, const int* in_sizes, int n_in,
                              void* d_out, int out_size) {
    const float *W0, *W1, *W2, *W3;
    const int *I0, *I1, *I2, *I3, *L0, *L1, *L2, *L3;

    if (in_sizes[2] == B_BAGS) {
        // interleaved (W0,ids0,lens0,W1,...)
        W0 = (const float*)d_in[0]; I0 = (const int*)d_in[1];  L0 = (const int*)d_in[2];
        W1 = (const float*)d_in[3]; I1 = (const int*)d_in[4];  L1 = (const int*)d_in[5];
        W2 = (const float*)d_in[6]; I2 = (const int*)d_in[7];  L2 = (const int*)d_in[8];
        W3 = (const float*)d_in[9]; I3 = (const int*)d_in[10]; L3 = (const int*)d_in[11];
    } else {
        // grouped (reference signature order)
        W0 = (const float*)d_in[0]; W1 = (const float*)d_in[1];
        W2 = (const float*)d_in[2]; W3 = (const float*)d_in[3];
        I0 = (const int*)d_in[4];   I1 = (const int*)d_in[5];
        I2 = (const int*)d_in[6];   I3 = (const int*)d_in[7];
        L0 = (const int*)d_in[8];   L1 = (const int*)d_in[9];
        L2 = (const int*)d_in[10];  L3 = (const int*)d_in[11];
    }

    float* out = (float*)d_out;

    scan_kernel<<<4, 1024>>>(L0, L1, L2, L3);
    pool_kernel<<<8192, 256>>>(W0, W1, W2, W3, I0, I1, I2, I3, out);
}